// round 7
// baseline (speedup 1.0000x reference)
#include <cuda_runtime.h>

// Problem constants (fixed by the dataset)
#define BB 4
#define NN 40960
#define KK 16
#define DOUT 16
#define BN_EPS 1e-5f

// Scratch: xyz padded to float4 so each neighbor gather is a single LDG.128.
// B*N = 163840 float4 = 2.62 MB. __device__ global => allocation-free.
__device__ float4 g_xyz4[BB * NN];

// --- Kernel 1: pack xyz [B,N,3] f32 -> float4 scratch ---------------------
__global__ void pack_xyz_kernel(const float* __restrict__ xyz) {
    int i = blockIdx.x * blockDim.x + threadIdx.x;
    if (i < BB * NN) {
        const float* p = xyz + 3 * i;
        g_xyz4[i] = make_float4(p[0], p[1], p[2], 0.0f);
    }
}

// --- Kernel 2: fused gather + relative-pos encode + conv1x1 + BN + ReLU ---
// Thread = one (b, n, group of 4 consecutive k). Writes 16 float4 (one per o).
// (256, 6): cap regs ~42 so 6 CTAs/SM = 48 warps -> hide 234-262cyc L2 gather
// latency (occ was 44.2%, issue 29.1% at regs=58).
__global__ __launch_bounds__(256, 6) void lse_kernel(
    const int* __restrict__ idx,         // [B,N,K] int32
    const float* __restrict__ W,         // [DOUT,10]
    const float* __restrict__ gamma,
    const float* __restrict__ beta,
    const float* __restrict__ rmean,
    const float* __restrict__ rvar,
    float* __restrict__ out)             // [B,DOUT,N,K]
{
    // Per-block prepped weights: y[o] = bias + w0*dist + A.tile + Bm.neigh
    __shared__ float sW0[DOUT];
    __shared__ float sA[DOUT][3];
    __shared__ float sBm[DOUT][3];
    __shared__ float sBias[DOUT];

    int t = threadIdx.x;
    if (t < DOUT) {
        float inv_std = rsqrtf(rvar[t] + BN_EPS);
        float sc = gamma[t] * inv_std;
        const float* w = W + t * 10;
        sW0[t] = w[0] * sc;
#pragma unroll
        for (int c = 0; c < 3; c++) {
            float wr = w[1 + c], wt = w[4 + c], wn = w[7 + c];
            sA[t][c]  = (wr + wt) * sc;   // coefficient of tile (center xyz)
            sBm[t][c] = (wn - wr) * sc;   // coefficient of neighbor xyz
        }
        sBias[t] = beta[t] - gamma[t] * rmean[t] * inv_std;
    }
    __syncthreads();

    int gid = blockIdx.x * blockDim.x + t;           // 0 .. B*N*K/4-1
    int b = gid / (NN * (KK / 4));                   // exact div, N*(K/4)=163840
    int r = gid - b * (NN * (KK / 4));
    int n = r >> 2;
    int k0 = (r & 3) << 2;                           // 0,4,8,12

    // 4 int32 neighbor indices in ONE LDG.128; streaming hint: the 10.5MB idx
    // stream has zero reuse -- keep it from evicting the L2-resident xyz.
    const int4 iv = __ldcs((const int4*)(idx + (b * NN + n) * KK + k0));

    const float4* xb = g_xyz4 + b * NN;
    float4 tile = xb[n];                             // broadcast across k-group

    // Random gathers: one LDG.128 each, working set 640 KB/batch -> L2 hits
    float4 nb0 = xb[iv.x];
    float4 nb1 = xb[iv.y];
    float4 nb2 = xb[iv.z];
    float4 nb3 = xb[iv.w];

    float rx0 = tile.x - nb0.x, ry0 = tile.y - nb0.y, rz0 = tile.z - nb0.z;
    float rx1 = tile.x - nb1.x, ry1 = tile.y - nb1.y, rz1 = tile.z - nb1.z;
    float rx2 = tile.x - nb2.x, ry2 = tile.y - nb2.y, rz2 = tile.z - nb2.z;
    float rx3 = tile.x - nb3.x, ry3 = tile.y - nb3.y, rz3 = tile.z - nb3.z;
    float d0 = sqrtf(rx0 * rx0 + ry0 * ry0 + rz0 * rz0);
    float d1 = sqrtf(rx1 * rx1 + ry1 * ry1 + rz1 * rz1);
    float d2 = sqrtf(rx2 * rx2 + ry2 * ry2 + rz2 * rz2);
    float d3 = sqrtf(rx3 * rx3 + ry3 * ry3 + rz3 * rz3);

    // out[((b*16+o)*N + n)*K + k0] ; per-o stride = N*K floats
    float* op = out + (b * DOUT * NN + n) * KK + k0;

#pragma unroll
    for (int o = 0; o < DOUT; o++) {
        float a0 = sA[o][0], a1 = sA[o][1], a2 = sA[o][2];
        float m0 = sBm[o][0], m1 = sBm[o][1], m2 = sBm[o][2];
        float w0 = sW0[o];
        // tile term shared by all 4 k
        float tt = sBias[o] + a0 * tile.x + a1 * tile.y + a2 * tile.z;

        float y0 = tt + w0 * d0 + m0 * nb0.x + m1 * nb0.y + m2 * nb0.z;
        float y1 = tt + w0 * d1 + m0 * nb1.x + m1 * nb1.y + m2 * nb1.z;
        float y2 = tt + w0 * d2 + m0 * nb2.x + m1 * nb2.y + m2 * nb2.z;
        float y3 = tt + w0 * d3 + m0 * nb3.x + m1 * nb3.y + m2 * nb3.z;

        float4 v = make_float4(fmaxf(y0, 0.0f), fmaxf(y1, 0.0f),
                               fmaxf(y2, 0.0f), fmaxf(y3, 0.0f));
        *(float4*)(op + o * (NN * KK)) = v;   // STG.128, warp-contiguous per o
    }
}

extern "C" void kernel_launch(void* const* d_in, const int* in_sizes, int n_in,
                              void* d_out, int out_size) {
    // Bind inputs by element count (robust to metadata ordering).
    const float* xyz = 0;
    const int*   idx = 0;
    const float* W   = 0;
    const float* p16[4] = {0, 0, 0, 0};   // gamma, beta, rmean, rvar in order
    int n16 = 0;

    for (int i = 0; i < n_in; i++) {
        switch (in_sizes[i]) {
            case BB * NN * 3:        xyz = (const float*)d_in[i]; break;   // 491520
            case BB * NN * KK:       idx = (const int*)d_in[i];   break;   // 2621440
            case DOUT * 10:          W   = (const float*)d_in[i]; break;   // 160
            case DOUT:               if (n16 < 4) p16[n16++] = (const float*)d_in[i]; break;
            default: break;           // feature (1310720): unused
        }
    }
    const float* gamma = p16[0];
    const float* beta  = p16[1];
    const float* rmean = p16[2];
    const float* rvar  = p16[3];
    float* out = (float*)d_out;
    (void)out_size;

    const int pack_total = BB * NN;                       // 163840
    pack_xyz_kernel<<<(pack_total + 511) / 512, 512>>>(xyz);

    const int total = BB * NN * (KK / 4);                 // 655360 threads
    lse_kernel<<<total / 256, 256>>>(idx, W, gamma, beta, rmean, rvar, out);
}

// round 8
// speedup vs baseline: 1.4835x; 1.4835x over previous
#include <cuda_runtime.h>

// Problem constants (fixed by the dataset)
#define BB 4
#define NN 40960
#define KK 16
#define DOUT 16
#define BN_EPS 1e-5f

// Scratch: xyz padded to float4 so each neighbor gather is a single LDG.128.
// B*N = 163840 float4 = 2.62 MB. __device__ global => allocation-free.
__device__ float4 g_xyz4[BB * NN];

// --- Kernel 1: pack xyz [B,N,3] f32 -> float4 scratch, 4 points/thread ----
// 3x LDG.128 in + 4x STG.128 out, fully coalesced. 40960 threads total.
__global__ void pack_xyz_kernel(const float4* __restrict__ xyz4) {
    int i = blockIdx.x * blockDim.x + threadIdx.x;   // 0 .. B*N/4-1
    if (i < BB * NN / 4) {
        float4 a = xyz4[3 * i + 0];   // x0 y0 z0 x1
        float4 b = xyz4[3 * i + 1];   // y1 z1 x2 y2
        float4 c = xyz4[3 * i + 2];   // z2 x3 y3 z3
        float4* o = g_xyz4 + 4 * i;
        o[0] = make_float4(a.x, a.y, a.z, 0.0f);
        o[1] = make_float4(a.w, b.x, b.y, 0.0f);
        o[2] = make_float4(b.z, b.w, c.x, 0.0f);
        o[3] = make_float4(c.y, c.z, c.w, 0.0f);
    }
}

// --- Kernel 2: fused gather + relative-pos encode + conv1x1 + BN + ReLU ---
// Thread = one (b, n, group of 4 consecutive k). Writes 16 float4 (one per o).
// NO reg cap: R7 showed capping regs kills gather MLP (serialized loads) and
// regresses 36->50us even at 70% occupancy. regs=58 / 32 warps is the sweet spot.
__global__ __launch_bounds__(256) void lse_kernel(
    const int* __restrict__ idx,         // [B,N,K] int32
    const float* __restrict__ W,         // [DOUT,10]
    const float* __restrict__ gamma,
    const float* __restrict__ beta,
    const float* __restrict__ rmean,
    const float* __restrict__ rvar,
    float* __restrict__ out)             // [B,DOUT,N,K]
{
    // Per-block prepped weights: y[o] = bias + w0*dist + A.tile + Bm.neigh
    __shared__ float sW0[DOUT];
    __shared__ float sA[DOUT][3];
    __shared__ float sBm[DOUT][3];
    __shared__ float sBias[DOUT];

    int t = threadIdx.x;
    if (t < DOUT) {
        float inv_std = rsqrtf(rvar[t] + BN_EPS);
        float sc = gamma[t] * inv_std;
        const float* w = W + t * 10;
        sW0[t] = w[0] * sc;
#pragma unroll
        for (int c = 0; c < 3; c++) {
            float wr = w[1 + c], wt = w[4 + c], wn = w[7 + c];
            sA[t][c]  = (wr + wt) * sc;   // coefficient of tile (center xyz)
            sBm[t][c] = (wn - wr) * sc;   // coefficient of neighbor xyz
        }
        sBias[t] = beta[t] - gamma[t] * rmean[t] * inv_std;
    }
    __syncthreads();

    int gid = blockIdx.x * blockDim.x + t;           // 0 .. B*N*K/4-1
    int b = gid / (NN * (KK / 4));                   // exact div, N*(K/4)=163840
    int r = gid - b * (NN * (KK / 4));
    int n = r >> 2;
    int k0 = (r & 3) << 2;                           // 0,4,8,12

    // Load 4 int32 neighbor indices in ONE LDG.128 (16B aligned)
    const int4 iv = *(const int4*)(idx + (b * NN + n) * KK + k0);

    const float4* xb = g_xyz4 + b * NN;
    float4 tile = xb[n];                             // broadcast across k-group

    // Random gathers: one LDG.128 each, working set 640 KB/batch -> L2 hits.
    // Keep all four front-batched (MLP=4+) -- this is the binding resource.
    float4 nb0 = xb[iv.x];
    float4 nb1 = xb[iv.y];
    float4 nb2 = xb[iv.z];
    float4 nb3 = xb[iv.w];

    float rx0 = tile.x - nb0.x, ry0 = tile.y - nb0.y, rz0 = tile.z - nb0.z;
    float rx1 = tile.x - nb1.x, ry1 = tile.y - nb1.y, rz1 = tile.z - nb1.z;
    float rx2 = tile.x - nb2.x, ry2 = tile.y - nb2.y, rz2 = tile.z - nb2.z;
    float rx3 = tile.x - nb3.x, ry3 = tile.y - nb3.y, rz3 = tile.z - nb3.z;
    float d0 = sqrtf(rx0 * rx0 + ry0 * ry0 + rz0 * rz0);
    float d1 = sqrtf(rx1 * rx1 + ry1 * ry1 + rz1 * rz1);
    float d2 = sqrtf(rx2 * rx2 + ry2 * ry2 + rz2 * rz2);
    float d3 = sqrtf(rx3 * rx3 + ry3 * ry3 + rz3 * rz3);

    // out[((b*16+o)*N + n)*K + k0] ; per-o stride = N*K floats
    float* op = out + (b * DOUT * NN + n) * KK + k0;

#pragma unroll
    for (int o = 0; o < DOUT; o++) {
        float a0 = sA[o][0], a1 = sA[o][1], a2 = sA[o][2];
        float m0 = sBm[o][0], m1 = sBm[o][1], m2 = sBm[o][2];
        float w0 = sW0[o];
        // tile term shared by all 4 k
        float tt = sBias[o] + a0 * tile.x + a1 * tile.y + a2 * tile.z;

        float y0 = tt + w0 * d0 + m0 * nb0.x + m1 * nb0.y + m2 * nb0.z;
        float y1 = tt + w0 * d1 + m0 * nb1.x + m1 * nb1.y + m2 * nb1.z;
        float y2 = tt + w0 * d2 + m0 * nb2.x + m1 * nb2.y + m2 * nb2.z;
        float y3 = tt + w0 * d3 + m0 * nb3.x + m1 * nb3.y + m2 * nb3.z;

        float4 v = make_float4(fmaxf(y0, 0.0f), fmaxf(y1, 0.0f),
                               fmaxf(y2, 0.0f), fmaxf(y3, 0.0f));
        // Streaming store: output is written once, never read -- evict-first
        // keeps L2 ways free for the hot 2.6MB xyz gather set.
        __stcs((float4*)(op + o * (NN * KK)), v);
    }
}

extern "C" void kernel_launch(void* const* d_in, const int* in_sizes, int n_in,
                              void* d_out, int out_size) {
    // Bind inputs by element count (robust to metadata ordering).
    const float* xyz = 0;
    const int*   idx = 0;
    const float* W   = 0;
    const float* p16[4] = {0, 0, 0, 0};   // gamma, beta, rmean, rvar in order
    int n16 = 0;

    for (int i = 0; i < n_in; i++) {
        switch (in_sizes[i]) {
            case BB * NN * 3:        xyz = (const float*)d_in[i]; break;   // 491520
            case BB * NN * KK:       idx = (const int*)d_in[i];   break;   // 2621440
            case DOUT * 10:          W   = (const float*)d_in[i]; break;   // 160
            case DOUT:               if (n16 < 4) p16[n16++] = (const float*)d_in[i]; break;
            default: break;           // feature (1310720): unused
        }
    }
    const float* gamma = p16[0];
    const float* beta  = p16[1];
    const float* rmean = p16[2];
    const float* rvar  = p16[3];
    float* out = (float*)d_out;
    (void)out_size;

    const int pack_threads = BB * NN / 4;                 // 40960
    pack_xyz_kernel<<<(pack_threads + 255) / 256, 256>>>((const float4*)xyz);

    const int total = BB * NN * (KK / 4);                 // 655360 threads
    lse_kernel<<<total / 256, 256>>>(idx, W, gamma, beta, rmean, rvar, out);
}